// round 16
// baseline (speedup 1.0000x reference)
#include <cuda_runtime.h>
#include <cuda_fp16.h>
#include <math.h>

// Problem constants
#define BB   8
#define NN   512
#define HID  512
#define HH   8
#define DD   64
#define EE   32
#define UU   16
#define M_TOT 4096
#define OUT_PART (BB * NN * HID)
#define NSQ  (NN * NN)
#define PAIRS ((long)BB * NN * NN)
#define MEAN_ELEMS (BB * NN * NN)

// ---------------- scratch (device globals) ----------------
__device__ __half g_x16[M_TOT * HID];
__device__ __half g_wq16[HID * HID];
__device__ __half g_wk16[HID * HID];
__device__ __half g_wv16[HID * HID];
__device__ __half g_wo16[HID * HID];
__device__ __half g_q16[M_TOT * HID];
__device__ __half g_k16[M_TOT * HID];
__device__ __half g_v16[M_TOT * HID];
__device__ __half g_ao16[M_TOT * HID];
__device__ __half g_eb16[BB * HH * NSQ];   // (B, H, N, N) fp16
__device__ int    g_mask_mode;

// ---------------- fast exp on FMA pipe ----------------
__device__ __forceinline__ float fast_exp(float x) {
    float t = x * 1.44269504f;
    t = fmaxf(t, -125.0f);
    int   ei = __float2int_rn(t);
    float f  = t - __int2float_rn(ei);
    float p  = 1.3333558e-3f;
    p = fmaf(p, f, 9.6181291e-3f);
    p = fmaf(p, f, 5.5504109e-2f);
    p = fmaf(p, f, 2.4022651e-1f);
    p = fmaf(p, f, 6.9314718e-1f);
    p = fmaf(p, f, 1.0f);
    return __int_as_float(__float_as_int(p) + (ei << 23));
}

// ---------------- mask dtype detection ----------------
__global__ void detect_mask_kernel(const unsigned int* __restrict__ bm) {
    __shared__ int sFloat, sHigh;
    if (threadIdx.x == 0) { sFloat = 0; sHigh = 0; }
    __syncthreads();
    unsigned int w = bm[threadIdx.x];
    if (w == 0x3F800000u) sFloat = 1;
    else if (w & 0xFFFFFF00u) sHigh = 1;
    __syncthreads();
    if (threadIdx.x == 0) g_mask_mode = (!sFloat && sHigh) ? 1 : 0;
}

// ---------------- zero kernel (float4) ----------------
__global__ void zero4_kernel(float4* __restrict__ p, int n4) {
    int i = blockIdx.x * blockDim.x + threadIdx.x;
    if (i < n4) p[i] = make_float4(0.f, 0.f, 0.f, 0.f);
}

// ---------------- fused fp32 -> fp16 convert (x + 4 weights) --------------
#define XF4 (M_TOT * HID / 4)      // 524288
#define WF4 (HID * HID / 4)        // 65536
__global__ void convert_all_kernel(const float* __restrict__ x,
                                   const float* __restrict__ Wq,
                                   const float* __restrict__ Wk,
                                   const float* __restrict__ Wv,
                                   const float* __restrict__ Wo) {
    int i = blockIdx.x * blockDim.x + threadIdx.x;
    const float* src; __half* dst; int off;
    if (i < XF4) { src = x; dst = g_x16; off = i; }
    else {
        int r = i - XF4;
        int seg = r >> 16;
        off = r & 65535;
        switch (seg) {
            case 0: src = Wq; dst = g_wq16; break;
            case 1: src = Wk; dst = g_wk16; break;
            case 2: src = Wv; dst = g_wv16; break;
            default: src = Wo; dst = g_wo16; break;
        }
    }
    float4 v = ((const float4*)src)[off];
    ((__half2*)dst)[2 * off]     = __float22half2_rn(make_float2(v.x, v.y));
    ((__half2*)dst)[2 * off + 1] = __float22half2_rn(make_float2(v.z, v.w));
}
#define CONV_TOT (XF4 + 4 * WF4)

// ---------------- mma helpers ----------------
__device__ __forceinline__ void ldmx4(unsigned& r0, unsigned& r1, unsigned& r2,
                                      unsigned& r3, const void* p) {
    unsigned a = (unsigned)__cvta_generic_to_shared(p);
    asm volatile("ldmatrix.sync.aligned.m8n8.x4.shared.b16 {%0,%1,%2,%3}, [%4];"
                 : "=r"(r0), "=r"(r1), "=r"(r2), "=r"(r3) : "r"(a));
}
__device__ __forceinline__ void ldmx4t(unsigned& r0, unsigned& r1, unsigned& r2,
                                       unsigned& r3, const void* p) {
    unsigned a = (unsigned)__cvta_generic_to_shared(p);
    asm volatile("ldmatrix.sync.aligned.m8n8.x4.trans.shared.b16 {%0,%1,%2,%3}, [%4];"
                 : "=r"(r0), "=r"(r1), "=r"(r2), "=r"(r3) : "r"(a));
}
__device__ __forceinline__ void ldmx2t(unsigned& r0, unsigned& r1, const void* p) {
    unsigned a = (unsigned)__cvta_generic_to_shared(p);
    asm volatile("ldmatrix.sync.aligned.m8n8.x2.trans.shared.b16 {%0,%1}, [%2];"
                 : "=r"(r0), "=r"(r1) : "r"(a));
}
__device__ __forceinline__ void mma16816(float* c, const unsigned* a,
                                         unsigned b0, unsigned b1) {
    asm volatile(
        "mma.sync.aligned.m16n8k16.row.col.f32.f16.f16.f32 "
        "{%0,%1,%2,%3}, {%4,%5,%6,%7}, {%8,%9}, {%0,%1,%2,%3};"
        : "+f"(c[0]), "+f"(c[1]), "+f"(c[2]), "+f"(c[3])
        : "r"(a[0]), "r"(a[1]), "r"(a[2]), "r"(a[3]), "r"(b0), "r"(b1));
}
__device__ __forceinline__ void cp16(void* sdst, const void* gsrc) {
    unsigned sa = (unsigned)__cvta_generic_to_shared(sdst);
    asm volatile("cp.async.ca.shared.global [%0], [%1], 16;" :: "r"(sa), "l"(gsrc));
}
__device__ __forceinline__ void cp_commit() { asm volatile("cp.async.commit_group;"); }

// ============ fp16 GEMM (3-stage cp.async pipeline) ==========
#define GBM 128
#define GBN 64
#define GBK 32

__global__ __launch_bounds__(256) void gemm_f16_kernel(
    const __half* __restrict__ A, const __half* __restrict__ Bw,
    const float* __restrict__ bias,
    const float* __restrict__ ct_emb, const int* __restrict__ ct_idx,
    void* __restrict__ Cout, int add_ct, int out_f16)
{
    __shared__ __align__(16) __half As[3][GBM][GBK + 8];
    __shared__ __align__(16) __half Bs[3][GBK][GBN + 8];

    const int tid  = threadIdx.x;
    const int m0   = blockIdx.y * GBM;
    const int n0   = blockIdx.x * GBN;
    const int warp = tid >> 5, lane = tid & 31;
    const int wm   = warp >> 1, wn = warp & 1;

    float acc[2][4][4];
#pragma unroll
    for (int i = 0; i < 2; i++)
#pragma unroll
        for (int j = 0; j < 4; j++)
#pragma unroll
            for (int f = 0; f < 4; f++) acc[i][j][f] = 0.0f;

    const int arow = tid >> 2, ac8 = (tid & 3) * 8;
    const int brow = tid >> 3, bc8 = (tid & 7) * 8;

    // prologue: stages 0, 1
#pragma unroll
    for (int s = 0; s < 2; s++) {
        const int k0 = s * GBK;
        cp16(&As[s][arow][ac8],      &A[(size_t)(m0 + arow) * 512 + k0 + ac8]);
        cp16(&As[s][arow + 64][ac8], &A[(size_t)(m0 + arow + 64) * 512 + k0 + ac8]);
        cp16(&Bs[s][brow][bc8],      &Bw[(size_t)(k0 + brow) * 512 + n0 + bc8]);
        cp_commit();
    }

    int buf = 0, nbuf = 2;
    for (int s = 0; s < 16; s++) {
        if (s + 2 < 16) {
            const int k0 = (s + 2) * GBK;
            cp16(&As[nbuf][arow][ac8],      &A[(size_t)(m0 + arow) * 512 + k0 + ac8]);
            cp16(&As[nbuf][arow + 64][ac8], &A[(size_t)(m0 + arow + 64) * 512 + k0 + ac8]);
            cp16(&Bs[nbuf][brow][bc8],      &Bw[(size_t)(k0 + brow) * 512 + n0 + bc8]);
            cp_commit();
            nbuf = (nbuf == 2) ? 0 : nbuf + 1;
            asm volatile("cp.async.wait_group 2;");
        } else if (s == 14) {
            asm volatile("cp.async.wait_group 1;");
        } else {
            asm volatile("cp.async.wait_group 0;");
        }
        __syncthreads();

#pragma unroll
        for (int ss = 0; ss < 2; ss++) {
            unsigned a[2][4], b[2][4];
#pragma unroll
            for (int mi = 0; mi < 2; mi++)
                ldmx4(a[mi][0], a[mi][1], a[mi][2], a[mi][3],
                      &As[buf][wm * 32 + mi * 16 + (lane & 15)][ss * 16 + (lane >> 4) * 8]);
#pragma unroll
            for (int p = 0; p < 2; p++)
                ldmx4t(b[p][0], b[p][1], b[p][2], b[p][3],
                       &Bs[buf][ss * 16 + ((lane >> 3) & 1) * 8 + (lane & 7)]
                              [wn * 32 + p * 16 + (lane >> 4) * 8]);
#pragma unroll
            for (int mi = 0; mi < 2; mi++)
#pragma unroll
                for (int nj = 0; nj < 4; nj++) {
                    int p = nj >> 1, hsel = nj & 1;
                    mma16816(acc[mi][nj], a[mi], b[p][2 * hsel], b[p][2 * hsel + 1]);
                }
        }
        __syncthreads();
        buf = (buf == 2) ? 0 : buf + 1;
    }

#pragma unroll
    for (int mi = 0; mi < 2; mi++) {
        int row = m0 + wm * 32 + mi * 16 + (lane >> 2);
        const float* cte  = add_ct ? &ct_emb[(size_t)ct_idx[row >> 9] * 512] : nullptr;
        const float* cte2 = add_ct ? &ct_emb[(size_t)ct_idx[(row + 8) >> 9] * 512] : nullptr;
#pragma unroll
        for (int nj = 0; nj < 4; nj++) {
            int col = n0 + wn * 32 + nj * 8 + (lane & 3) * 2;
            float b0 = bias[col], b1 = bias[col + 1];
            float c0 = acc[mi][nj][0] + b0, c1 = acc[mi][nj][1] + b1;
            float c2 = acc[mi][nj][2] + b0, c3 = acc[mi][nj][3] + b1;
            if (add_ct) {
                c0 += cte[col];  c1 += cte[col + 1];
                c2 += cte2[col]; c3 += cte2[col + 1];
            }
            if (out_f16) {
                __half* C16 = (__half*)Cout;
                *(__half2*)&C16[(size_t)row * 512 + col]       = __float22half2_rn(make_float2(c0, c1));
                *(__half2*)&C16[(size_t)(row + 8) * 512 + col] = __float22half2_rn(make_float2(c2, c3));
            } else {
                float* Cf = (float*)Cout;
                *(float2*)&Cf[(size_t)row * 512 + col]       = make_float2(c0, c1);
                *(float2*)&Cf[(size_t)(row + 8) * 512 + col] = make_float2(c2, c3);
            }
        }
    }
}

// ---------------- edge MLP (HFMA2 stage1 + fast-exp ELU, fp16 out) --------
__global__ __launch_bounds__(256) void edge_mlp_kernel(
    const float* __restrict__ ef, const float* __restrict__ W1,
    const float* __restrict__ b1, const float* __restrict__ W2,
    const float* __restrict__ b2)
{
    __shared__ __half2 w1h[EE][8];
    __shared__ float w2_s[UU][HH];
    __shared__ float b1_s[UU];
    __shared__ float b2_s[HH];

    const int tid = threadIdx.x;
    {
        int k = tid >> 3, u2 = tid & 7;
        w1h[k][u2] = __float22half2_rn(make_float2(W1[k * 16 + 2 * u2], W1[k * 16 + 2 * u2 + 1]));
    }
    if (tid < UU * HH) ((float*)w2_s)[tid] = W2[tid];
    if (tid < UU) b1_s[tid] = b1[tid];
    if (tid < HH) b2_s[tid] = b2[tid];
    __syncthreads();

    const long p = (long)blockIdx.x * 256 + tid;

    float e[EE];
#pragma unroll
    for (int i = 0; i < EE / 4; i++) {
        float4 v = *(const float4*)&ef[p * EE + i * 4];
        e[i * 4 + 0] = v.x; e[i * 4 + 1] = v.y;
        e[i * 4 + 2] = v.z; e[i * 4 + 3] = v.w;
    }

    __half2 h2[8];
#pragma unroll
    for (int u = 0; u < 8; u++)
        h2[u] = __float22half2_rn(make_float2(b1_s[2 * u], b1_s[2 * u + 1]));
#pragma unroll
    for (int k = 0; k < EE; k++) {
        __half2 e2 = __float2half2_rn(e[k]);
#pragma unroll
        for (int u = 0; u < 8; u++) h2[u] = __hfma2(e2, w1h[k][u], h2[u]);
    }

    float o[HH];
#pragma unroll
    for (int oo = 0; oo < HH; oo++) o[oo] = b2_s[oo];
#pragma unroll
    for (int u = 0; u < 8; u++) {
        float2 hf = __half22float2(h2[u]);
        float ha = (hf.x > 0.0f) ? hf.x : (fast_exp(hf.x) - 1.0f);
        float hb = (hf.y > 0.0f) ? hf.y : (fast_exp(hf.y) - 1.0f);
#pragma unroll
        for (int oo = 0; oo < HH; oo++)
            o[oo] += ha * w2_s[2 * u][oo] + hb * w2_s[2 * u + 1][oo];
    }

    const size_t bidx = (size_t)(p >> 18);
    const size_t rem  = (size_t)(p & (NSQ - 1));
#pragma unroll
    for (int oo = 0; oo < HH; oo++)
        g_eb16[(bidx * HH + oo) * (size_t)NSQ + rem] = __float2half_rn(o[oo]);
}

// ---------------- fused attention: block per (b, tile, head-group of 4) ---
#define SST 520
#define KVH 72
__global__ __launch_bounds__(256) void attn_kernel(
    const void* __restrict__ block_mask_raw,
    const void* __restrict__ pad_mask_raw,
    float* __restrict__ mean_out)
{
    extern __shared__ unsigned char dynsmem[];
    float*  S  = (float*)dynsmem;                                  // 33280 B
    __half* Pb = (__half*)(dynsmem + 33280);                       // 16640 B
    __half* kv = (__half*)(dynsmem + 33280 + 16640);               // 36864 B
    __half* qs = (__half*)(dynsmem + 33280 + 16640 + 36864);       // 2304 B

    __shared__ unsigned int maskbits[16][16];

    const int tid  = threadIdx.x;
    const int warp = tid >> 5, lane = tid & 31;
    const int idx  = blockIdx.x;
    const int hg   = idx & 1;                 // head group 0..1
    const int i0   = ((idx >> 1) & 31) * 16;
    const int b    = idx >> 6;
    const int mode = g_mask_mode;

    const unsigned int*  bm_w = (const unsigned int*)block_mask_raw;
    const unsigned char* bm_b = (const unsigned char*)block_mask_raw;
    const unsigned int*  pm_w = (const unsigned int*)pad_mask_raw;
    const unsigned char* pm_b = (const unsigned char*)pad_mask_raw;

    // combined mask bits (bm | padi | padj), decoded once
    {
        int r = tid >> 4, w = tid & 15;
        size_t gi = (size_t)(b * NN + i0 + r);
        bool pi = mode ? (pm_b[gi] != 0) : (pm_w[gi] != 0u);
        unsigned int bits = 0;
        for (int k = 0; k < 32; k++) {
            int j = w * 32 + k;
            bool pj = mode ? (pm_b[b * NN + j] != 0) : (pm_w[b * NN + j] != 0u);
            bool bmv = mode ? (bm_b[gi * NN + j] != 0) : (bm_w[gi * NN + j] != 0u);
            if (bmv || pi || pj) bits |= (1u << k);
        }
        maskbits[r][w] = bits;
    }
    float mean_acc[2][16];
#pragma unroll
    for (int rr = 0; rr < 2; rr++)
#pragma unroll
        for (int c = 0; c < 16; c++) mean_acc[rr][c] = 0.0f;
    __syncthreads();

    for (int h = hg * 4; h < hg * 4 + 4; h++) {
        // ---- prefill S with eb (fp16) / -inf ----
        const size_t ebrow0 = ((size_t)(b * HH + h) * NN + i0) * NN;
        for (int x = tid; x < 1024; x += 256) {
            int r = x >> 6, j8 = (x & 63) * 8;
            unsigned int bits = maskbits[r][j8 >> 5] >> (j8 & 31);
            uint4 raw = *(const uint4*)&g_eb16[ebrow0 + (size_t)r * NN + j8];
            __half2* hp = (__half2*)&raw;
            float2 f0 = __half22float2(hp[0]);
            float2 f1 = __half22float2(hp[1]);
            float2 f2 = __half22float2(hp[2]);
            float2 f3 = __half22float2(hp[3]);
            float4 s0, s1;
            s0.x = (bits &   1u) ? -INFINITY : f0.x;
            s0.y = (bits &   2u) ? -INFINITY : f0.y;
            s0.z = (bits &   4u) ? -INFINITY : f1.x;
            s0.w = (bits &   8u) ? -INFINITY : f1.y;
            s1.x = (bits &  16u) ? -INFINITY : f2.x;
            s1.y = (bits &  32u) ? -INFINITY : f2.y;
            s1.z = (bits &  64u) ? -INFINITY : f3.x;
            s1.w = (bits & 128u) ? -INFINITY : f3.y;
            *(float4*)&S[r * SST + j8]     = s0;
            *(float4*)&S[r * SST + j8 + 4] = s1;
        }
        if (tid < 128) {
            int row = tid >> 3, c8 = (tid & 7) * 8;
            *(uint4*)&qs[row * KVH + c8] =
                *(const uint4*)&g_q16[((size_t)(b * NN + i0 + row)) * HID + h * DD + c8];
        }
        __syncthreads();

        unsigned aq[4][4];
#pragma unroll
        for (int ks = 0; ks < 4; ks++)
            ldmx4(aq[ks][0], aq[ks][1], aq[ks][2], aq[ks][3],
                  &qs[(lane & 15) * KVH + ks * 16 + (lane >> 4) * 8]);

        // ---- QK^T ----
        for (int jt = 0; jt < 2; jt++) {
            for (int i = tid; i < 2048; i += 256) {
                int row = i >> 3, c8 = (i & 7) * 8;
                *(uint4*)&kv[row * KVH + c8] =
                    *(const uint4*)&g_k16[((size_t)(b * NN + jt * 256 + row)) * HID + h * DD + c8];
            }
            __syncthreads();

            float cacc[4][4];
#pragma unroll
            for (int i = 0; i < 4; i++)
#pragma unroll
                for (int j = 0; j < 4; j++) cacc[i][j] = 0.0f;

#pragma unroll
            for (int ks = 0; ks < 4; ks++) {
#pragma unroll
                for (int np = 0; np < 2; np++) {
                    unsigned r0, r1, r2, r3;
                    ldmx4(r0, r1, r2, r3,
                          &kv[(warp * 32 + np * 16 + ((lane >> 4) << 3) + (lane & 7)) * KVH
                              + ks * 16 + ((lane >> 3) & 1) * 8]);
                    mma16816(cacc[np * 2],     aq[ks], r0, r1);
                    mma16816(cacc[np * 2 + 1], aq[ks], r2, r3);
                }
            }
            int row0 = lane >> 2;
#pragma unroll
            for (int nt = 0; nt < 4; nt++) {
                int j = jt * 256 + warp * 32 + nt * 8 + (lane & 3) * 2;
                S[row0 * SST + j]           += cacc[nt][0] * 0.125f;
                S[row0 * SST + j + 1]       += cacc[nt][1] * 0.125f;
                S[(row0 + 8) * SST + j]     += cacc[nt][2] * 0.125f;
                S[(row0 + 8) * SST + j + 1] += cacc[nt][3] * 0.125f;
            }
            __syncthreads();
        }

        // ---- softmax + mean (FMA-pipe exp) ----
#pragma unroll
        for (int rr = 0; rr < 2; rr++) {
            int r = warp + rr * 8;
            float vals[16];
            float m = -INFINITY;
#pragma unroll
            for (int c = 0; c < 16; c++) {
                vals[c] = S[r * SST + lane + 32 * c];
                m = fmaxf(m, vals[c]);
            }
#pragma unroll
            for (int off = 16; off; off >>= 1)
                m = fmaxf(m, __shfl_xor_sync(0xffffffffu, m, off));
            float sum = 0.0f;
            if (m == -INFINITY) {
#pragma unroll
                for (int c = 0; c < 16; c++) vals[c] = 0.0f;
            } else {
#pragma unroll
                for (int c = 0; c < 16; c++) { vals[c] = fast_exp(vals[c] - m); sum += vals[c]; }
            }
#pragma unroll
            for (int off = 16; off; off >>= 1)
                sum += __shfl_xor_sync(0xffffffffu, sum, off);
            float inv = (sum > 0.0f) ? (1.0f / sum) : 0.0f;
#pragma unroll
            for (int c = 0; c < 16; c++) {
                float pv = vals[c] * inv;
                Pb[r * SST + lane + 32 * c] = __float2half(pv);
                mean_acc[rr][c] += pv;
            }
        }
        __syncthreads();

        // ---- P @ V ----
        float oacc[4] = {0.0f, 0.0f, 0.0f, 0.0f};
        const int d0 = warp * 8;
        for (int jt = 0; jt < 2; jt++) {
            for (int i = tid; i < 2048; i += 256) {
                int row = i >> 3, c8 = (i & 7) * 8;
                *(uint4*)&kv[row * KVH + c8] =
                    *(const uint4*)&g_v16[((size_t)(b * NN + jt * 256 + row)) * HID + h * DD + c8];
            }
            __syncthreads();
#pragma unroll
            for (int ks = 0; ks < 16; ks++) {
                unsigned ap0, ap1, ap2, ap3, v0, v1;
                ldmx4(ap0, ap1, ap2, ap3,
                      &Pb[(lane & 15) * SST + jt * 256 + ks * 16 + (lane >> 4) * 8]);
                ldmx2t(v0, v1, &kv[(ks * 16 + (lane & 15)) * KVH + d0]);
                unsigned ap[4] = {ap0, ap1, ap2, ap3};
                mma16816(oacc, ap, v0, v1);
            }
            __syncthreads();
        }
        {
            int row = lane >> 2, col = d0 + (lane & 3) * 2;
            __half* dst0 = &g_ao16[((size_t)(b * NN + i0 + row)) * HID + h * DD + col];
            __half* dst1 = &g_ao16[((size_t)(b * NN + i0 + row + 8)) * HID + h * DD + col];
            *(__half2*)dst0 = __float22half2_rn(make_float2(oacc[0], oacc[1]));
            *(__half2*)dst1 = __float22half2_rn(make_float2(oacc[2], oacc[3]));
        }
        __syncthreads();
    }

    // ---- accumulate partial mean (2 contenders per address) ----
#pragma unroll
    for (int rr = 0; rr < 2; rr++) {
        int row = i0 + warp + rr * 8;
        size_t base = ((size_t)(b * NN + row)) * NN;
#pragma unroll
        for (int c = 0; c < 16; c++)
            atomicAdd(&mean_out[base + lane + 32 * c], mean_acc[rr][c] * 0.125f);
    }
}

// ---------------- stream/event context (created once at load) -------------
struct OverlapCtx {
    cudaStream_t s2 = nullptr;
    cudaEvent_t  e1 = nullptr, e2 = nullptr;
    bool ok = false;
    OverlapCtx() {
        ok = (cudaStreamCreateWithFlags(&s2, cudaStreamNonBlocking) == cudaSuccess) &&
             (cudaEventCreateWithFlags(&e1, cudaEventDisableTiming) == cudaSuccess) &&
             (cudaEventCreateWithFlags(&e2, cudaEventDisableTiming) == cudaSuccess);
    }
};
static OverlapCtx g_ovl;

// ---------------- launch ----------------
extern "C" void kernel_launch(void* const* d_in, const int* in_sizes, int n_in,
                              void* d_out, int out_size)
{
    const float* x    = (const float*)d_in[0];
    const int*   ct   = (const int*)d_in[1];
    const float* ef   = (const float*)d_in[2];
    const void*  block_mask = d_in[3];
    const void*  pad_mask   = d_in[4];
    const float* Wq = (const float*)d_in[5];
    const float* bq = (const float*)d_in[6];
    const float* Wk = (const float*)d_in[7];
    const float* bk = (const float*)d_in[8];
    const float* Wv = (const float*)d_in[9];
    const float* bv = (const float*)d_in[10];
    const float* Wo = (const float*)d_in[11];
    const float* bo = (const float*)d_in[12];
    const float* We1 = (const float*)d_in[13];
    const float* be1 = (const float*)d_in[14];
    const float* We2 = (const float*)d_in[15];
    const float* be2 = (const float*)d_in[16];
    const float* ct_key  = (const float*)d_in[17];

    float* out_main = (float*)d_out;
    float* out_mean = out_main + OUT_PART;

    __half *x16, *wq16, *wk16, *wv16, *wo16, *q16, *k16, *v16, *ao16;
    cudaGetSymbolAddress((void**)&x16,  g_x16);
    cudaGetSymbolAddress((void**)&wq16, g_wq16);
    cudaGetSymbolAddress((void**)&wk16, g_wk16);
    cudaGetSymbolAddress((void**)&wv16, g_wv16);
    cudaGetSymbolAddress((void**)&wo16, g_wo16);
    cudaGetSymbolAddress((void**)&q16,  g_q16);
    cudaGetSymbolAddress((void**)&k16,  g_k16);
    cudaGetSymbolAddress((void**)&v16,  g_v16);
    cudaGetSymbolAddress((void**)&ao16, g_ao16);

    const int attn_smem = 33280 + 16640 + 36864 + 2304;  // 89088
    cudaFuncSetAttribute(attn_kernel, cudaFuncAttributeMaxDynamicSharedMemorySize, attn_smem);

    const bool ovl = g_ovl.ok;

    // 0) mask dtype detect + zero mean (main stream)
    detect_mask_kernel<<<1, 256>>>((const unsigned int*)block_mask);
    zero4_kernel<<<(MEAN_ELEMS / 4 + 255) / 256, 256>>>((float4*)out_mean, MEAN_ELEMS / 4);

    // fork: edge MLP on side stream (DRAM-bound) overlaps projections (tensor-bound)
    if (ovl) {
        cudaEventRecord(g_ovl.e1, 0);
        cudaStreamWaitEvent(g_ovl.s2, g_ovl.e1, 0);
        edge_mlp_kernel<<<(int)(PAIRS / 256), 256, 0, g_ovl.s2>>>(ef, We1, be1, We2, be2);
        cudaEventRecord(g_ovl.e2, g_ovl.s2);
    }

    // 1) fused fp16 conversions + projections (main stream)
    convert_all_kernel<<<(CONV_TOT + 255) / 256, 256>>>(x, Wq, Wk, Wv, Wo);
    dim3 ggrid(512 / GBN, M_TOT / GBM);
    gemm_f16_kernel<<<ggrid, 256>>>(x16, wq16, bq, ct_key, ct, q16, 0, 1);
    gemm_f16_kernel<<<ggrid, 256>>>(x16, wk16, bk, ct_key, ct, k16, 1, 1);
    gemm_f16_kernel<<<ggrid, 256>>>(x16, wv16, bv, ct_key, ct, v16, 0, 1);

    if (ovl) {
        cudaStreamWaitEvent(0, g_ovl.e2, 0);   // join edge before attn
    } else {
        edge_mlp_kernel<<<(int)(PAIRS / 256), 256>>>(ef, We1, be1, We2, be2);
    }

    // 3) fused attention (512 blocks: head-group split, partial-mean atomics)
    attn_kernel<<<BB * 32 * 2, 256, attn_smem>>>(block_mask, pad_mask, out_mean);

    // 4) output projection
    gemm_f16_kernel<<<ggrid, 256>>>(ao16, wo16, bo, ct_key, ct, out_main, 0, 0);
}